// round 6
// baseline (speedup 1.0000x reference)
#include <cuda_runtime.h>
#include <cstdint>
#include <math.h>

// Problem constants
#define BB 2
#define SS 2048
#define DD 2048
#define HH 16
#define DH 128
#define N3 6144   // 3 * DD
#define MM (BB * SS)   // 4096

// Scratch (allocation-free rule: __device__ globals)
__device__ float g_qkv[(size_t)BB * SS * N3];      // ~100 MB
__device__ float g_att[(size_t)BB * SS * DD];      // ~33 MB
__device__ float g_xr[(size_t)MM * DD];            // ~33 MB  tf32-rounded x
__device__ float g_wqkvT[(size_t)N3 * DD];         // ~50 MB  W_qkv^T (rounded)
__device__ float g_woutT[(size_t)DD * DD];         // ~16 MB  W_out^T (rounded)

// ---------------------------------------------------------------------------
// Helpers
// ---------------------------------------------------------------------------
__device__ __forceinline__ uint32_t smem_to_u32(const void* p) {
    uint32_t a;
    asm("{ .reg .u64 t; cvta.to.shared.u64 t, %1; cvt.u32.u64 %0, t; }"
        : "=r"(a) : "l"(p));
    return a;
}
__device__ __forceinline__ float round_tf32(float f) {
    uint32_t u;
    asm("cvt.rna.tf32.f32 %0, %1;" : "=r"(u) : "f"(f));
    return __uint_as_float(u);
}
// D += A*B  (m16n8k8 tf32, row.col)
__device__ __forceinline__ void mma_tf32(float* d, const uint32_t* a, const uint32_t* b) {
    asm volatile(
        "mma.sync.aligned.m16n8k8.row.col.f32.tf32.tf32.f32 "
        "{%0,%1,%2,%3}, {%4,%5,%6,%7}, {%8,%9}, {%0,%1,%2,%3};"
        : "+f"(d[0]), "+f"(d[1]), "+f"(d[2]), "+f"(d[3])
        : "r"(a[0]), "r"(a[1]), "r"(a[2]), "r"(a[3]), "r"(b[0]), "r"(b[1]));
}

// ---------------------------------------------------------------------------
// tf32 pre-round pass (elementwise, float4)
// ---------------------------------------------------------------------------
__global__ __launch_bounds__(256) void round_pass_kernel(
    const float4* __restrict__ in, float4* __restrict__ out, int n4)
{
    int i = blockIdx.x * 256 + threadIdx.x;
    if (i < n4) {
        float4 v = in[i];
        v.x = round_tf32(v.x); v.y = round_tf32(v.y);
        v.z = round_tf32(v.z); v.w = round_tf32(v.w);
        out[i] = v;
    }
}

// ---------------------------------------------------------------------------
// Transpose + tf32 round: in [R, C] -> out [C, R]
// ---------------------------------------------------------------------------
__global__ __launch_bounds__(256) void transpose_kernel(
    const float* __restrict__ in, float* __restrict__ out, int R, int C)
{
    __shared__ float t[32][33];
    const int bx = blockIdx.x * 32, by = blockIdx.y * 32;
    const int tx = threadIdx.x & 31, ty4 = (threadIdx.x >> 5) * 4;
    #pragma unroll
    for (int j = 0; j < 4; j++)
        t[ty4 + j][tx] = in[(size_t)(by + ty4 + j) * C + bx + tx];
    __syncthreads();
    #pragma unroll
    for (int j = 0; j < 4; j++)
        out[(size_t)(bx + ty4 + j) * R + by + tx] = round_tf32(t[tx][ty4 + j]);
}

// ---------------------------------------------------------------------------
// tf32 mma.sync GEMM:  C[M,N] = A[M,K] @ Bt[N,K]^T + bias[N]
// CTA tile 128(M) x 256(N), 8 warps (2m x 4n), warp tile 64x64, KC=32,
// double-buffered cp.async. Smem stride 36 -> conflict-free fragment LDS.
// ---------------------------------------------------------------------------
#define KC 32
#define SST 36
#define TILE_A_F (128 * SST)               // 4608 floats
#define TILE_B_F (256 * SST)               // 9216 floats
#define STAGE_F  (TILE_A_F + TILE_B_F)     // 13824 floats
#define GEMM_SMEM_BYTES (2 * STAGE_F * 4)  // 110592 B

__global__ __launch_bounds__(256, 1) void tf32_mma_gemm(
    const float* __restrict__ A, const float* __restrict__ Bt,
    const float* __restrict__ bias, float* __restrict__ C,
    int M, int N, int K)
{
    extern __shared__ float smf[];
    const uint32_t smem_base = smem_to_u32(smf);
    const int tid  = threadIdx.x;
    const int wid  = tid >> 5;
    const int lane = tid & 31;
    const int g    = lane >> 2;      // 0..7
    const int tq   = lane & 3;       // 0..3
    const int wm   = wid >> 2;       // 0..1  (64-row slabs)
    const int wn   = wid & 3;        // 0..3  (64-col slabs)
    const int m0 = blockIdx.y * 128;
    const int n0 = blockIdx.x * 256;

    float d[4][8][4];
    #pragma unroll
    for (int mt = 0; mt < 4; mt++)
        #pragma unroll
        for (int nt = 0; nt < 8; nt++)
            #pragma unroll
            for (int j = 0; j < 4; j++) d[mt][nt][j] = 0.f;

    const int NT = K / KC;

    auto load_stage = [&](int t) {
        const int buf = t & 1;
        const int k0  = t * KC;
        const float* Ab = A + (size_t)m0 * K + k0;
        const float* Bb = Bt + (size_t)n0 * K + k0;
        const uint32_t da = smem_base + (uint32_t)buf * (STAGE_F * 4);
        const uint32_t db = da + TILE_A_F * 4;
        #pragma unroll
        for (int i = 0; i < 4; i++) {
            const int idx = i * 256 + tid;
            const int row = idx >> 3, q = idx & 7;
            const uint32_t dsta = da + ((uint32_t)row * SST + q * 4) * 4;
            const float* ga = Ab + (size_t)row * K + q * 4;
            asm volatile("cp.async.cg.shared.global [%0], [%1], 16;" :: "r"(dsta), "l"(ga));
        }
        #pragma unroll
        for (int i = 0; i < 8; i++) {
            const int idx = i * 256 + tid;
            const int row = idx >> 3, q = idx & 7;
            const uint32_t dstb = db + ((uint32_t)row * SST + q * 4) * 4;
            const float* gb = Bb + (size_t)row * K + q * 4;
            asm volatile("cp.async.cg.shared.global [%0], [%1], 16;" :: "r"(dstb), "l"(gb));
        }
    };

    load_stage(0);
    asm volatile("cp.async.commit_group;" ::: "memory");
    load_stage(1);
    asm volatile("cp.async.commit_group;" ::: "memory");

    for (int t = 0; t < NT; t++) {
        const int buf = t & 1;
        asm volatile("cp.async.wait_group 1;" ::: "memory");
        __syncthreads();

        const float* as = smf + buf * STAGE_F + (wm * 64) * SST;
        const float* bs = smf + buf * STAGE_F + TILE_A_F + (wn * 64) * SST;

        #pragma unroll
        for (int kk = 0; kk < 4; kk++) {
            const int k = kk * 8;
            uint32_t af[4][4];
            #pragma unroll
            for (int mt = 0; mt < 4; mt++) {
                const float* p = as + (mt * 16 + g) * SST + k + tq;
                af[mt][0] = __float_as_uint(p[0]);
                af[mt][1] = __float_as_uint(p[8 * SST]);
                af[mt][2] = __float_as_uint(p[4]);
                af[mt][3] = __float_as_uint(p[8 * SST + 4]);
            }
            uint32_t bf[8][2];
            #pragma unroll
            for (int nt = 0; nt < 8; nt++) {
                const float* p = bs + (nt * 8 + g) * SST + k + tq;
                bf[nt][0] = __float_as_uint(p[0]);
                bf[nt][1] = __float_as_uint(p[4]);
            }
            #pragma unroll
            for (int mt = 0; mt < 4; mt++)
                #pragma unroll
                for (int nt = 0; nt < 8; nt++)
                    mma_tf32(d[mt][nt], af[mt], bf[nt]);
        }

        __syncthreads();
        if (t + 2 < NT) load_stage(t + 2);
        asm volatile("cp.async.commit_group;" ::: "memory");
    }

    // Epilogue: bias + store
    #pragma unroll
    for (int mt = 0; mt < 4; mt++) {
        const int row0 = m0 + wm * 64 + mt * 16 + g;
        #pragma unroll
        for (int nt = 0; nt < 8; nt++) {
            const int col = n0 + wn * 64 + nt * 8 + tq * 2;
            const float2 bv = *(const float2*)(bias + col);
            float2 v0, v1;
            v0.x = d[mt][nt][0] + bv.x; v0.y = d[mt][nt][1] + bv.y;
            v1.x = d[mt][nt][2] + bv.x; v1.y = d[mt][nt][3] + bv.y;
            *(float2*)(C + (size_t)row0 * N + col)       = v0;
            *(float2*)(C + (size_t)(row0 + 8) * N + col) = v1;
        }
    }
}

// ---------------------------------------------------------------------------
// Tensor-core flash attention (causal, tf32 mma.sync).
// One CTA per (b, h, 128-row Q tile); 8 warps, each owns 16 Q rows.
// ---------------------------------------------------------------------------
#define AQ 128
#define AK 64
#define AST 132
#define APSTR 68
#define AQ_OFF 0
#define AK_OFF (AQ * AST)
#define AV_OFF (AK_OFF + AK * AST)
#define AP_OFF (AV_OFF + AK * AST)
#define ATT2_FLOATS (AP_OFF + AQ * APSTR)
#define ATT2_BYTES (ATT2_FLOATS * 4)

__global__ __launch_bounds__(256, 1) void attn_tc_kernel()
{
    extern __shared__ float sm[];
    const int tid  = threadIdx.x;
    const int w    = tid >> 5;
    const int lane = tid & 31;
    const int g    = lane >> 2;
    const int tq   = lane & 3;

    const int b  = blockIdx.z;
    const int h  = blockIdx.y;
    const int qt = (SS / AQ - 1) - blockIdx.x;
    const int q0 = qt * AQ;
    const int rw = w * 16;

    const float qscale = 0.08838834764831845f;
    const size_t base = (size_t)b * SS * N3 + (size_t)h * DH;

    #pragma unroll
    for (int it = 0; it < 16; it++) {
        const int idx = it * 256 + tid;
        const int row = idx >> 5;
        const int c4  = (idx & 31) * 4;
        float4 v = *(const float4*)(g_qkv + base + (size_t)(q0 + row) * N3 + c4);
        v.x = round_tf32(v.x * qscale); v.y = round_tf32(v.y * qscale);
        v.z = round_tf32(v.z * qscale); v.w = round_tf32(v.w * qscale);
        *(float4*)&sm[AQ_OFF + row * AST + c4] = v;
    }

    float m0 = -1e30f, m1 = -1e30f, l0 = 0.f, l1 = 0.f;
    float o[16][4];
    #pragma unroll
    for (int dt = 0; dt < 16; dt++)
        #pragma unroll
        for (int j = 0; j < 4; j++) o[dt][j] = 0.f;

    const int nkt = 2 * qt + 2;
    for (int kt = 0; kt < nkt; kt++) {
        const int k0 = kt * AK;
        __syncthreads();

        #pragma unroll
        for (int it = 0; it < 8; it++) {
            const int idx = it * 256 + tid;
            const int row = idx >> 5;
            const int c4  = (idx & 31) * 4;
            const float* src = g_qkv + base + (size_t)(k0 + row) * N3 + c4;
            float4 kv = *(const float4*)(src + DD);
            float4 vv = *(const float4*)(src + 2 * DD);
            kv.x = round_tf32(kv.x); kv.y = round_tf32(kv.y);
            kv.z = round_tf32(kv.z); kv.w = round_tf32(kv.w);
            vv.x = round_tf32(vv.x); vv.y = round_tf32(vv.y);
            vv.z = round_tf32(vv.z); vv.w = round_tf32(vv.w);
            *(float4*)&sm[AK_OFF + row * AST + c4] = kv;
            *(float4*)&sm[AV_OFF + row * AST + c4] = vv;
        }
        __syncthreads();

        float s[8][4];
        #pragma unroll
        for (int nt = 0; nt < 8; nt++)
            #pragma unroll
            for (int j = 0; j < 4; j++) s[nt][j] = 0.f;

        #pragma unroll
        for (int kk = 0; kk < 16; kk++) {
            uint32_t af[4];
            const float* qp = sm + AQ_OFF + (rw + g) * AST + kk * 8 + tq;
            af[0] = __float_as_uint(qp[0]);
            af[1] = __float_as_uint(qp[8 * AST]);
            af[2] = __float_as_uint(qp[4]);
            af[3] = __float_as_uint(qp[8 * AST + 4]);
            #pragma unroll
            for (int nt = 0; nt < 8; nt++) {
                uint32_t bf[2];
                const float* kp = sm + AK_OFF + (nt * 8 + g) * AST + kk * 8 + tq;
                bf[0] = __float_as_uint(kp[0]);
                bf[1] = __float_as_uint(kp[4]);
                mma_tf32(s[nt], af, bf);
            }
        }

        if (k0 + 63 > q0) {
            const int r0 = q0 + rw + g, r1 = r0 + 8;
            #pragma unroll
            for (int nt = 0; nt < 8; nt++) {
                const int c = k0 + nt * 8 + 2 * tq;
                if (c     > r0) s[nt][0] = -1e30f;
                if (c + 1 > r0) s[nt][1] = -1e30f;
                if (c     > r1) s[nt][2] = -1e30f;
                if (c + 1 > r1) s[nt][3] = -1e30f;
            }
        }

        float nm0 = m0, nm1 = m1;
        #pragma unroll
        for (int nt = 0; nt < 8; nt++) {
            nm0 = fmaxf(nm0, fmaxf(s[nt][0], s[nt][1]));
            nm1 = fmaxf(nm1, fmaxf(s[nt][2], s[nt][3]));
        }
        nm0 = fmaxf(nm0, __shfl_xor_sync(0xffffffffu, nm0, 1));
        nm0 = fmaxf(nm0, __shfl_xor_sync(0xffffffffu, nm0, 2));
        nm1 = fmaxf(nm1, __shfl_xor_sync(0xffffffffu, nm1, 1));
        nm1 = fmaxf(nm1, __shfl_xor_sync(0xffffffffu, nm1, 2));
        const float a0 = __expf(m0 - nm0);
        const float a1 = __expf(m1 - nm1);
        m0 = nm0; m1 = nm1;

        float rs0 = 0.f, rs1 = 0.f;
        #pragma unroll
        for (int nt = 0; nt < 8; nt++) {
            s[nt][0] = __expf(s[nt][0] - m0);
            s[nt][1] = __expf(s[nt][1] - m0);
            s[nt][2] = __expf(s[nt][2] - m1);
            s[nt][3] = __expf(s[nt][3] - m1);
            rs0 += s[nt][0] + s[nt][1];
            rs1 += s[nt][2] + s[nt][3];
        }
        rs0 += __shfl_xor_sync(0xffffffffu, rs0, 1);
        rs0 += __shfl_xor_sync(0xffffffffu, rs0, 2);
        rs1 += __shfl_xor_sync(0xffffffffu, rs1, 1);
        rs1 += __shfl_xor_sync(0xffffffffu, rs1, 2);
        l0 = l0 * a0 + rs0;
        l1 = l1 * a1 + rs1;

        #pragma unroll
        for (int dt = 0; dt < 16; dt++) {
            o[dt][0] *= a0; o[dt][1] *= a0;
            o[dt][2] *= a1; o[dt][3] *= a1;
        }
        #pragma unroll
        for (int nt = 0; nt < 8; nt++) {
            float2 p0, p1;
            p0.x = round_tf32(s[nt][0]); p0.y = round_tf32(s[nt][1]);
            p1.x = round_tf32(s[nt][2]); p1.y = round_tf32(s[nt][3]);
            *(float2*)&sm[AP_OFF + (rw + g) * APSTR + nt * 8 + 2 * tq]     = p0;
            *(float2*)&sm[AP_OFF + (rw + g + 8) * APSTR + nt * 8 + 2 * tq] = p1;
        }
        __syncthreads();

        #pragma unroll
        for (int kk = 0; kk < 8; kk++) {
            uint32_t af[4];
            const float* pp = sm + AP_OFF + (rw + g) * APSTR + kk * 8 + tq;
            af[0] = __float_as_uint(pp[0]);
            af[1] = __float_as_uint(pp[8 * APSTR]);
            af[2] = __float_as_uint(pp[4]);
            af[3] = __float_as_uint(pp[8 * APSTR + 4]);
            #pragma unroll
            for (int nt = 0; nt < 16; nt++) {
                uint32_t bf[2];
                const float* vp = sm + AV_OFF + (kk * 8 + tq) * AST + nt * 8 + g;
                bf[0] = __float_as_uint(vp[0]);
                bf[1] = __float_as_uint(vp[4 * AST]);
                mma_tf32(o[nt], af, bf);
            }
        }
    }

    const float i0 = 1.f / l0, i1 = 1.f / l1;
    const int r0 = q0 + rw + g, r1 = r0 + 8;
    #pragma unroll
    for (int dt = 0; dt < 16; dt++) {
        const int c = h * DH + dt * 8 + 2 * tq;
        float2 v0, v1;
        v0.x = round_tf32(o[dt][0] * i0); v0.y = round_tf32(o[dt][1] * i0);
        v1.x = round_tf32(o[dt][2] * i1); v1.y = round_tf32(o[dt][3] * i1);
        *(float2*)(g_att + ((size_t)b * SS + r0) * DD + c) = v0;
        *(float2*)(g_att + ((size_t)b * SS + r1) * DD + c) = v1;
    }
}

// ---------------------------------------------------------------------------
// Launch
// ---------------------------------------------------------------------------
extern "C" void kernel_launch(void* const* d_in, const int* in_sizes, int n_in,
                              void* d_out, int out_size)
{
    const float* x     = (const float*)d_in[0];
    const float* W_qkv = (const float*)d_in[1];
    const float* b_qkv = (const float*)d_in[2];
    const float* W_out = (const float*)d_in[3];
    const float* b_out = (const float*)d_in[4];
    float* out = (float*)d_out;

    float *qkv_ptr, *att_ptr, *xr_ptr, *wqkvT_ptr, *woutT_ptr;
    cudaGetSymbolAddress((void**)&qkv_ptr,   g_qkv);
    cudaGetSymbolAddress((void**)&att_ptr,   g_att);
    cudaGetSymbolAddress((void**)&xr_ptr,    g_xr);
    cudaGetSymbolAddress((void**)&wqkvT_ptr, g_wqkvT);
    cudaGetSymbolAddress((void**)&woutT_ptr, g_woutT);

    static bool attr_done = false;
    if (!attr_done) {
        cudaFuncSetAttribute(tf32_mma_gemm,
                             cudaFuncAttributeMaxDynamicSharedMemorySize,
                             GEMM_SMEM_BYTES);
        cudaFuncSetAttribute(attn_tc_kernel,
                             cudaFuncAttributeMaxDynamicSharedMemorySize,
                             ATT2_BYTES);
        attr_done = true;
    }

    // 0) tf32 pre-rounding: x elementwise; weights transposed+rounded
    {
        const int n4 = MM * DD / 4;
        round_pass_kernel<<<(n4 + 255) / 256, 256>>>(
            (const float4*)x, (float4*)xr_ptr, n4);
        transpose_kernel<<<dim3(N3 / 32, DD / 32), 256>>>(W_qkv, wqkvT_ptr, DD, N3);
        transpose_kernel<<<dim3(DD / 32, DD / 32), 256>>>(W_out, woutT_ptr, DD, DD);
    }

    // 1) QKV projection (tf32 mma.sync)
    tf32_mma_gemm<<<dim3(N3 / 256, MM / 128), 256, GEMM_SMEM_BYTES>>>(
        xr_ptr, wqkvT_ptr, b_qkv, qkv_ptr, MM, N3, DD);

    // 2) Causal flash attention (tf32 tensor cores)
    attn_tc_kernel<<<dim3(SS / AQ, HH, BB), 256, ATT2_BYTES>>>();

    // 3) Output projection (tf32 mma.sync)
    tf32_mma_gemm<<<dim3(DD / 256, MM / 128), 256, GEMM_SMEM_BYTES>>>(
        att_ptr, woutT_ptr, b_out, out, MM, DD, DD);
}

// round 7
// speedup vs baseline: 1.5465x; 1.5465x over previous
#include <cuda_runtime.h>
#include <cstdint>
#include <math.h>

// Problem constants
#define BB 2
#define SS 2048
#define DD 2048
#define HH 16
#define DH 128
#define N3 6144   // 3 * DD
#define MM (BB * SS)   // 4096

// Scratch (allocation-free rule: __device__ globals)
__device__ float g_qkv[(size_t)BB * SS * N3];      // ~100 MB
__device__ float g_att[(size_t)BB * SS * DD];      // ~33 MB
__device__ float g_xr[(size_t)MM * DD];            // ~33 MB  tf32-rounded x
__device__ float g_wqkvT[(size_t)N3 * DD];         // ~50 MB  W_qkv^T (rounded)
__device__ float g_woutT[(size_t)DD * DD];         // ~16 MB  W_out^T (rounded)

// ---------------------------------------------------------------------------
// Helpers
// ---------------------------------------------------------------------------
__device__ __forceinline__ uint32_t smem_to_u32(const void* p) {
    uint32_t a;
    asm("{ .reg .u64 t; cvta.to.shared.u64 t, %1; cvt.u32.u64 %0, t; }"
        : "=r"(a) : "l"(p));
    return a;
}
__device__ __forceinline__ float round_tf32(float f) {
    uint32_t u;
    asm("cvt.rna.tf32.f32 %0, %1;" : "=r"(u) : "f"(f));
    return __uint_as_float(u);
}
// D += A*B  (m16n8k8 tf32, row.col)
__device__ __forceinline__ void mma_tf32(float* d, const uint32_t* a, const uint32_t* b) {
    asm volatile(
        "mma.sync.aligned.m16n8k8.row.col.f32.tf32.tf32.f32 "
        "{%0,%1,%2,%3}, {%4,%5,%6,%7}, {%8,%9}, {%0,%1,%2,%3};"
        : "+f"(d[0]), "+f"(d[1]), "+f"(d[2]), "+f"(d[3])
        : "r"(a[0]), "r"(a[1]), "r"(a[2]), "r"(a[3]), "r"(b[0]), "r"(b[1]));
}

// ---------------------------------------------------------------------------
// tf32 pre-round pass (elementwise, float4)
// ---------------------------------------------------------------------------
__global__ __launch_bounds__(256) void round_pass_kernel(
    const float4* __restrict__ in, float4* __restrict__ out, int n4)
{
    int i = blockIdx.x * 256 + threadIdx.x;
    if (i < n4) {
        float4 v = in[i];
        v.x = round_tf32(v.x); v.y = round_tf32(v.y);
        v.z = round_tf32(v.z); v.w = round_tf32(v.w);
        out[i] = v;
    }
}

// ---------------------------------------------------------------------------
// Transpose + tf32 round: in [R, C] -> out [C, R]
// ---------------------------------------------------------------------------
__global__ __launch_bounds__(256) void transpose_kernel(
    const float* __restrict__ in, float* __restrict__ out, int R, int C)
{
    __shared__ float t[32][33];
    const int bx = blockIdx.x * 32, by = blockIdx.y * 32;
    const int tx = threadIdx.x & 31, ty4 = (threadIdx.x >> 5) * 4;
    #pragma unroll
    for (int j = 0; j < 4; j++)
        t[ty4 + j][tx] = in[(size_t)(by + ty4 + j) * C + bx + tx];
    __syncthreads();
    #pragma unroll
    for (int j = 0; j < 4; j++)
        out[(size_t)(bx + ty4 + j) * R + by + tx] = round_tf32(t[tx][ty4 + j]);
}

// ---------------------------------------------------------------------------
// tf32 mma.sync GEMM:  C[M,N] = A[M,K] @ Bt[N,K]^T + bias[N]
// 128x128 CTA tile, 8 warps (2m x 4n), warp tile 64x32, KC=32.
// THREE-stage cp.async pipeline, ONE __syncthreads per K-chunk.
// 110592 B smem/CTA -> 2 CTAs/SM.
// ---------------------------------------------------------------------------
#define KC 32
#define SST 36
#define TILE_F (128 * SST)                  // 4608 floats per A or B tile
#define STAGE_F (2 * TILE_F)                // 9216 floats per stage
#define GEMM_SMEM_BYTES (3 * STAGE_F * 4)   // 110592

__global__ __launch_bounds__(256, 2) void tf32_mma_gemm(
    const float* __restrict__ A, const float* __restrict__ Bt,
    const float* __restrict__ bias, float* __restrict__ C,
    int M, int N, int K)
{
    extern __shared__ float smf[];
    const uint32_t smem_base = smem_to_u32(smf);
    const int tid  = threadIdx.x;
    const int wid  = tid >> 5;
    const int lane = tid & 31;
    const int g    = lane >> 2;
    const int tq   = lane & 3;
    const int wm   = wid >> 2;
    const int wn   = wid & 3;
    const int m0 = blockIdx.y * 128;
    const int n0 = blockIdx.x * 128;

    float d[4][4][4];
    #pragma unroll
    for (int mt = 0; mt < 4; mt++)
        #pragma unroll
        for (int nt = 0; nt < 4; nt++)
            #pragma unroll
            for (int j = 0; j < 4; j++) d[mt][nt][j] = 0.f;

    const int NT = K / KC;

    auto load_stage = [&](int t, int buf) {
        const int k0 = t * KC;
        const float* Ab = A + (size_t)m0 * K + k0;
        const float* Bb = Bt + (size_t)n0 * K + k0;
        const uint32_t da = smem_base + (uint32_t)buf * (STAGE_F * 4);
        const uint32_t db = da + TILE_F * 4;
        #pragma unroll
        for (int i = 0; i < 4; i++) {
            const int idx = i * 256 + tid;
            const int row = idx >> 3, q = idx & 7;
            const uint32_t dsta = da + ((uint32_t)row * SST + q * 4) * 4;
            const float* ga = Ab + (size_t)row * K + q * 4;
            asm volatile("cp.async.cg.shared.global [%0], [%1], 16;" :: "r"(dsta), "l"(ga));
            const uint32_t dstb = db + ((uint32_t)row * SST + q * 4) * 4;
            const float* gb = Bb + (size_t)row * K + q * 4;
            asm volatile("cp.async.cg.shared.global [%0], [%1], 16;" :: "r"(dstb), "l"(gb));
        }
    };

    load_stage(0, 0);
    asm volatile("cp.async.commit_group;" ::: "memory");
    load_stage(1, 1);
    asm volatile("cp.async.commit_group;" ::: "memory");

    int buf = 0;        // buffer of chunk t
    int buf2 = 2;       // buffer for chunk t+2
    for (int t = 0; t < NT; t++) {
        asm volatile("cp.async.wait_group 1;" ::: "memory");
        __syncthreads();

        // Prefetch chunk t+2 into a buffer disjoint from t (compute) and t+1.
        if (t + 2 < NT) load_stage(t + 2, buf2);
        asm volatile("cp.async.commit_group;" ::: "memory");

        const float* as = smf + buf * STAGE_F + (wm * 64) * SST;
        const float* bs = smf + buf * STAGE_F + TILE_F + (wn * 32) * SST;

        #pragma unroll
        for (int kk = 0; kk < 4; kk++) {
            const int k = kk * 8;
            uint32_t af[4][4];
            #pragma unroll
            for (int mt = 0; mt < 4; mt++) {
                const float* p = as + (mt * 16 + g) * SST + k + tq;
                af[mt][0] = __float_as_uint(p[0]);
                af[mt][1] = __float_as_uint(p[8 * SST]);
                af[mt][2] = __float_as_uint(p[4]);
                af[mt][3] = __float_as_uint(p[8 * SST + 4]);
            }
            uint32_t bf[4][2];
            #pragma unroll
            for (int nt = 0; nt < 4; nt++) {
                const float* p = bs + (nt * 8 + g) * SST + k + tq;
                bf[nt][0] = __float_as_uint(p[0]);
                bf[nt][1] = __float_as_uint(p[4]);
            }
            #pragma unroll
            for (int mt = 0; mt < 4; mt++)
                #pragma unroll
                for (int nt = 0; nt < 4; nt++)
                    mma_tf32(d[mt][nt], af[mt], bf[nt]);
        }

        buf  = (buf  == 2) ? 0 : buf + 1;
        buf2 = (buf2 == 2) ? 0 : buf2 + 1;
    }

    // Epilogue: bias + store
    #pragma unroll
    for (int mt = 0; mt < 4; mt++) {
        const int row0 = m0 + wm * 64 + mt * 16 + g;
        #pragma unroll
        for (int nt = 0; nt < 4; nt++) {
            const int col = n0 + wn * 32 + nt * 8 + tq * 2;
            const float2 bv = *(const float2*)(bias + col);
            float2 v0, v1;
            v0.x = d[mt][nt][0] + bv.x; v0.y = d[mt][nt][1] + bv.y;
            v1.x = d[mt][nt][2] + bv.x; v1.y = d[mt][nt][3] + bv.y;
            *(float2*)(C + (size_t)row0 * N + col)       = v0;
            *(float2*)(C + (size_t)(row0 + 8) * N + col) = v1;
        }
    }
}

// ---------------------------------------------------------------------------
// Tensor-core flash attention (causal, tf32 mma.sync).
// One CTA per (b, h, 128-row Q tile); 8 warps, each owns 16 Q rows.
// ---------------------------------------------------------------------------
#define AQ 128
#define AK 64
#define AST 132
#define APSTR 68
#define AQ_OFF 0
#define AK_OFF (AQ * AST)
#define AV_OFF (AK_OFF + AK * AST)
#define AP_OFF (AV_OFF + AK * AST)
#define ATT2_FLOATS (AP_OFF + AQ * APSTR)
#define ATT2_BYTES (ATT2_FLOATS * 4)

__global__ __launch_bounds__(256, 1) void attn_tc_kernel()
{
    extern __shared__ float sm[];
    const int tid  = threadIdx.x;
    const int w    = tid >> 5;
    const int lane = tid & 31;
    const int g    = lane >> 2;
    const int tq   = lane & 3;

    const int b  = blockIdx.z;
    const int h  = blockIdx.y;
    const int qt = (SS / AQ - 1) - blockIdx.x;
    const int q0 = qt * AQ;
    const int rw = w * 16;

    const float qscale = 0.08838834764831845f;
    const size_t base = (size_t)b * SS * N3 + (size_t)h * DH;

    #pragma unroll
    for (int it = 0; it < 16; it++) {
        const int idx = it * 256 + tid;
        const int row = idx >> 5;
        const int c4  = (idx & 31) * 4;
        float4 v = *(const float4*)(g_qkv + base + (size_t)(q0 + row) * N3 + c4);
        v.x = round_tf32(v.x * qscale); v.y = round_tf32(v.y * qscale);
        v.z = round_tf32(v.z * qscale); v.w = round_tf32(v.w * qscale);
        *(float4*)&sm[AQ_OFF + row * AST + c4] = v;
    }

    float m0 = -1e30f, m1 = -1e30f, l0 = 0.f, l1 = 0.f;
    float o[16][4];
    #pragma unroll
    for (int dt = 0; dt < 16; dt++)
        #pragma unroll
        for (int j = 0; j < 4; j++) o[dt][j] = 0.f;

    const int nkt = 2 * qt + 2;
    for (int kt = 0; kt < nkt; kt++) {
        const int k0 = kt * AK;
        __syncthreads();

        #pragma unroll
        for (int it = 0; it < 8; it++) {
            const int idx = it * 256 + tid;
            const int row = idx >> 5;
            const int c4  = (idx & 31) * 4;
            const float* src = g_qkv + base + (size_t)(k0 + row) * N3 + c4;
            float4 kv = *(const float4*)(src + DD);
            float4 vv = *(const float4*)(src + 2 * DD);
            kv.x = round_tf32(kv.x); kv.y = round_tf32(kv.y);
            kv.z = round_tf32(kv.z); kv.w = round_tf32(kv.w);
            vv.x = round_tf32(vv.x); vv.y = round_tf32(vv.y);
            vv.z = round_tf32(vv.z); vv.w = round_tf32(vv.w);
            *(float4*)&sm[AK_OFF + row * AST + c4] = kv;
            *(float4*)&sm[AV_OFF + row * AST + c4] = vv;
        }
        __syncthreads();

        float s[8][4];
        #pragma unroll
        for (int nt = 0; nt < 8; nt++)
            #pragma unroll
            for (int j = 0; j < 4; j++) s[nt][j] = 0.f;

        #pragma unroll
        for (int kk = 0; kk < 16; kk++) {
            uint32_t af[4];
            const float* qp = sm + AQ_OFF + (rw + g) * AST + kk * 8 + tq;
            af[0] = __float_as_uint(qp[0]);
            af[1] = __float_as_uint(qp[8 * AST]);
            af[2] = __float_as_uint(qp[4]);
            af[3] = __float_as_uint(qp[8 * AST + 4]);
            #pragma unroll
            for (int nt = 0; nt < 8; nt++) {
                uint32_t bf[2];
                const float* kp = sm + AK_OFF + (nt * 8 + g) * AST + kk * 8 + tq;
                bf[0] = __float_as_uint(kp[0]);
                bf[1] = __float_as_uint(kp[4]);
                mma_tf32(s[nt], af, bf);
            }
        }

        if (k0 + 63 > q0) {
            const int r0 = q0 + rw + g, r1 = r0 + 8;
            #pragma unroll
            for (int nt = 0; nt < 8; nt++) {
                const int c = k0 + nt * 8 + 2 * tq;
                if (c     > r0) s[nt][0] = -1e30f;
                if (c + 1 > r0) s[nt][1] = -1e30f;
                if (c     > r1) s[nt][2] = -1e30f;
                if (c + 1 > r1) s[nt][3] = -1e30f;
            }
        }

        float nm0 = m0, nm1 = m1;
        #pragma unroll
        for (int nt = 0; nt < 8; nt++) {
            nm0 = fmaxf(nm0, fmaxf(s[nt][0], s[nt][1]));
            nm1 = fmaxf(nm1, fmaxf(s[nt][2], s[nt][3]));
        }
        nm0 = fmaxf(nm0, __shfl_xor_sync(0xffffffffu, nm0, 1));
        nm0 = fmaxf(nm0, __shfl_xor_sync(0xffffffffu, nm0, 2));
        nm1 = fmaxf(nm1, __shfl_xor_sync(0xffffffffu, nm1, 1));
        nm1 = fmaxf(nm1, __shfl_xor_sync(0xffffffffu, nm1, 2));
        const float a0 = __expf(m0 - nm0);
        const float a1 = __expf(m1 - nm1);
        m0 = nm0; m1 = nm1;

        float rs0 = 0.f, rs1 = 0.f;
        #pragma unroll
        for (int nt = 0; nt < 8; nt++) {
            s[nt][0] = __expf(s[nt][0] - m0);
            s[nt][1] = __expf(s[nt][1] - m0);
            s[nt][2] = __expf(s[nt][2] - m1);
            s[nt][3] = __expf(s[nt][3] - m1);
            rs0 += s[nt][0] + s[nt][1];
            rs1 += s[nt][2] + s[nt][3];
        }
        rs0 += __shfl_xor_sync(0xffffffffu, rs0, 1);
        rs0 += __shfl_xor_sync(0xffffffffu, rs0, 2);
        rs1 += __shfl_xor_sync(0xffffffffu, rs1, 1);
        rs1 += __shfl_xor_sync(0xffffffffu, rs1, 2);
        l0 = l0 * a0 + rs0;
        l1 = l1 * a1 + rs1;

        #pragma unroll
        for (int dt = 0; dt < 16; dt++) {
            o[dt][0] *= a0; o[dt][1] *= a0;
            o[dt][2] *= a1; o[dt][3] *= a1;
        }
        #pragma unroll
        for (int nt = 0; nt < 8; nt++) {
            float2 p0, p1;
            p0.x = round_tf32(s[nt][0]); p0.y = round_tf32(s[nt][1]);
            p1.x = round_tf32(s[nt][2]); p1.y = round_tf32(s[nt][3]);
            *(float2*)&sm[AP_OFF + (rw + g) * APSTR + nt * 8 + 2 * tq]     = p0;
            *(float2*)&sm[AP_OFF + (rw + g + 8) * APSTR + nt * 8 + 2 * tq] = p1;
        }
        __syncthreads();

        #pragma unroll
        for (int kk = 0; kk < 8; kk++) {
            uint32_t af[4];
            const float* pp = sm + AP_OFF + (rw + g) * APSTR + kk * 8 + tq;
            af[0] = __float_as_uint(pp[0]);
            af[1] = __float_as_uint(pp[8 * APSTR]);
            af[2] = __float_as_uint(pp[4]);
            af[3] = __float_as_uint(pp[8 * APSTR + 4]);
            #pragma unroll
            for (int nt = 0; nt < 16; nt++) {
                uint32_t bf[2];
                const float* vp = sm + AV_OFF + (kk * 8 + tq) * AST + nt * 8 + g;
                bf[0] = __float_as_uint(vp[0]);
                bf[1] = __float_as_uint(vp[4 * AST]);
                mma_tf32(o[nt], af, bf);
            }
        }
    }

    const float i0 = 1.f / l0, i1 = 1.f / l1;
    const int r0 = q0 + rw + g, r1 = r0 + 8;
    #pragma unroll
    for (int dt = 0; dt < 16; dt++) {
        const int c = h * DH + dt * 8 + 2 * tq;
        float2 v0, v1;
        v0.x = round_tf32(o[dt][0] * i0); v0.y = round_tf32(o[dt][1] * i0);
        v1.x = round_tf32(o[dt][2] * i1); v1.y = round_tf32(o[dt][3] * i1);
        *(float2*)(g_att + ((size_t)b * SS + r0) * DD + c) = v0;
        *(float2*)(g_att + ((size_t)b * SS + r1) * DD + c) = v1;
    }
}

// ---------------------------------------------------------------------------
// Launch
// ---------------------------------------------------------------------------
extern "C" void kernel_launch(void* const* d_in, const int* in_sizes, int n_in,
                              void* d_out, int out_size)
{
    const float* x     = (const float*)d_in[0];
    const float* W_qkv = (const float*)d_in[1];
    const float* b_qkv = (const float*)d_in[2];
    const float* W_out = (const float*)d_in[3];
    const float* b_out = (const float*)d_in[4];
    float* out = (float*)d_out;

    float *qkv_ptr, *att_ptr, *xr_ptr, *wqkvT_ptr, *woutT_ptr;
    cudaGetSymbolAddress((void**)&qkv_ptr,   g_qkv);
    cudaGetSymbolAddress((void**)&att_ptr,   g_att);
    cudaGetSymbolAddress((void**)&xr_ptr,    g_xr);
    cudaGetSymbolAddress((void**)&wqkvT_ptr, g_wqkvT);
    cudaGetSymbolAddress((void**)&woutT_ptr, g_woutT);

    static bool attr_done = false;
    if (!attr_done) {
        cudaFuncSetAttribute(tf32_mma_gemm,
                             cudaFuncAttributeMaxDynamicSharedMemorySize,
                             GEMM_SMEM_BYTES);
        cudaFuncSetAttribute(attn_tc_kernel,
                             cudaFuncAttributeMaxDynamicSharedMemorySize,
                             ATT2_BYTES);
        attr_done = true;
    }

    // 0) tf32 pre-rounding: x elementwise; weights transposed+rounded
    {
        const int n4 = MM * DD / 4;
        round_pass_kernel<<<(n4 + 255) / 256, 256>>>(
            (const float4*)x, (float4*)xr_ptr, n4);
        transpose_kernel<<<dim3(N3 / 32, DD / 32), 256>>>(W_qkv, wqkvT_ptr, DD, N3);
        transpose_kernel<<<dim3(DD / 32, DD / 32), 256>>>(W_out, woutT_ptr, DD, DD);
    }

    // 1) QKV projection (tf32 mma.sync)
    tf32_mma_gemm<<<dim3(N3 / 128, MM / 128), 256, GEMM_SMEM_BYTES>>>(
        xr_ptr, wqkvT_ptr, b_qkv, qkv_ptr, MM, N3, DD);

    // 2) Causal flash attention (tf32 tensor cores)
    attn_tc_kernel<<<dim3(SS / AQ, HH, BB), 256, ATT2_BYTES>>>();

    // 3) Output projection (tf32 mma.sync)
    tf32_mma_gemm<<<dim3(DD / 128, MM / 128), 256, GEMM_SMEM_BYTES>>>(
        att_ptr, woutT_ptr, b_out, out, MM, DD, DD);
}